// round 15
// baseline (speedup 1.0000x reference)
#include <cuda_runtime.h>
#include <cuda_fp16.h>

#define MAXN 50000
#define MAXE 1600000
#define MAXEP (MAXE + 15 * MAXN)  // padded CSR capacity (rows rounded to 16)
#define NBLK 256

// ---------------- scratch (device globals; no allocation) ----------------
__device__ __half2 g_hh[(MAXN + 1) * 32]; // fp16 x@Wg; row=64 halfs=128B; row n stays 0
__device__ float   g_acc[MAXN * 64];      // x @ W_res + b_gat + b_res (fp32)
__device__ float   g_asrc[(MAXN + 1) * 4];// row MAXN = -1e30 sentinel (w -> 0)
__device__ float   g_adst[MAXN * 4];
__device__ int     g_cnt[MAXN];           // in-degree (self-cleaned by k_agg)
__device__ int     g_off[MAXN];           // row starts (16-aligned)
__device__ int     g_total;               // bump counter (self-cleaned by k_agg)
__device__ int     g_rank[MAXE];          // per-edge within-dst rank
__device__ int     g_srcs[MAXEP];         // CSR src ids (+ sentinel pads)

// leaky_relu(v,0.2): for v<0, 0.2v > v, so max(v,0.2v) == leaky
__device__ __forceinline__ float eweight(float v) {
    return __expf(fmaxf(v, 0.2f * v));
}
__device__ __forceinline__ float4 h8tof4(uint2 u) {
    __half2 lo = *reinterpret_cast<__half2*>(&u.x);
    __half2 hi = *reinterpret_cast<__half2*>(&u.y);
    float2 a = __half22float2(lo), b = __half22float2(hi);
    return make_float4(a.x, a.y, b.x, b.y);
}
__device__ __forceinline__ unsigned long long pack2(float v) {
    unsigned long long r;
    asm("mov.b64 %0, {%1, %1};" : "=l"(r) : "f"(v));
    return r;
}
__device__ __forceinline__ void fma2(unsigned long long& acc, unsigned long long a,
                                     unsigned long long b) {
    asm("fma.rn.f32x2 %0, %1, %2, %0;" : "+l"(acc) : "l"(a), "l"(b));
}
__device__ __forceinline__ float2 unpack2(unsigned long long v) {
    float2 r;
    asm("mov.b64 {%0, %1}, %2;" : "=f"(r.x), "=f"(r.y) : "l"(v));
    return r;
}

// ---------------------------------------------------------------------------
// K1: fused dual GEMM with packed f32x2 FMAs (proven R14):
//   g_hh = fp16(x@Wg) (+ attention logits), g_acc = x@Wr + b_gat + b_res.
// ---------------------------------------------------------------------------
__global__ void k_gemm(const float* __restrict__ x,
                       const float* __restrict__ Wg, const float* __restrict__ Wr,
                       const float* __restrict__ b0, const float* __restrict__ b1,
                       const float* __restrict__ att_s, const float* __restrict__ att_d,
                       int n) {
    extern __shared__ float sm[];
    float* sWg = sm;
    float* sWr = sm + 8192;
    float* xs  = sm + 16384;
    int tid = threadIdx.x;
    for (int i = tid; i < 8192; i += NBLK) { sWg[i] = Wg[i]; sWr[i] = Wr[i]; }
    int base = blockIdx.x * 32;
    const float4* x4 = (const float4*)x;
    for (int i = tid; i < 32 * 32; i += NBLK) {
        int node = i >> 5, kk = i & 31;
        float4 v = make_float4(0.f, 0.f, 0.f, 0.f);
        if (base + node < n) v = x4[(base + node) * 32 + kk];
        ((float4*)xs)[i] = v;
    }
    __syncthreads();

    int tx = tid & 31;
    int ty = tid >> 5;
    unsigned long long AG[4] = {0ull, 0ull, 0ull, 0ull};
    unsigned long long AR[4] = {0ull, 0ull, 0ull, 0ull};
    const float* xp = xs + ty * 4 * 128;
    const unsigned long long* wgp = (const unsigned long long*)sWg;  // 32 ull per k-row
    const unsigned long long* wrp = (const unsigned long long*)sWr;
#pragma unroll 4
    for (int k = 0; k < 128; k++) {
        unsigned long long wg = wgp[k * 32 + tx];
        unsigned long long wr = wrp[k * 32 + tx];
#pragma unroll
        for (int i = 0; i < 4; i++) {
            unsigned long long xx = pack2(xp[i * 128 + k]);
            fma2(AG[i], wg, xx);
            fma2(AR[i], wr, xx);
        }
    }

    float bias0 = b0[2 * tx] + b1[2 * tx];
    float bias1 = b0[2 * tx + 1] + b1[2 * tx + 1];
    float as0 = att_s[2 * tx], as1 = att_s[2 * tx + 1];
    float ad0 = att_d[2 * tx], ad1 = att_d[2 * tx + 1];
    int hd = tx >> 3;
#pragma unroll
    for (int i = 0; i < 4; i++) {
        int node = base + ty * 4 + i;
        float2 g = unpack2(AG[i]);
        float2 r = unpack2(AR[i]);
        float ps = g.x * as0 + g.y * as1;
        float pd = g.x * ad0 + g.y * ad1;
#pragma unroll
        for (int off = 4; off; off >>= 1) {
            ps += __shfl_xor_sync(0xffffffffu, ps, off);
            pd += __shfl_xor_sync(0xffffffffu, pd, off);
        }
        if (node < n) {
            g_hh[node * 32 + tx] = __floats2half2_rn(g.x, g.y);
            ((float2*)(g_acc + node * 64))[tx] = make_float2(r.x + bias0, r.y + bias1);
            if ((tx & 7) == 0) {
                g_asrc[node * 4 + hd] = ps;
                g_adst[node * 4 + hd] = pd;
            }
        }
    }
}

// ---------------------------------------------------------------------------
// K2: degree histogram + per-edge rank capture (overlapped with GEMM)
// ---------------------------------------------------------------------------
__global__ void k_hist(const int* __restrict__ ei, int E) {
    int i = blockIdx.x * NBLK + threadIdx.x;
    if (i < E) g_rank[i] = atomicAdd(&g_cnt[ei[E + i]], 1);
}

// ---------------------------------------------------------------------------
// K3: row starts (warp bump alloc, rows padded to 16; pads src = n sentinel).
// Also writes the sentinel asrc row.
// ---------------------------------------------------------------------------
__global__ void k_rows(int n) {
    int i = blockIdx.x * NBLK + threadIdx.x;
    int lane = threadIdx.x & 31;
    if (i < 4) g_asrc[n * 4 + i] = -1e30f;   // sentinel: weight -> 0
    int deg = (i < n) ? g_cnt[i] : 0;
    int sz = (deg + 15) & ~15;
    int sc = sz;
#pragma unroll
    for (int off = 1; off < 32; off <<= 1) {
        int t = __shfl_up_sync(0xffffffffu, sc, off);
        if (lane >= off) sc += t;
    }
    int tot = __shfl_sync(0xffffffffu, sc, 31);
    int rb = 0;
    if (lane == 31) rb = atomicAdd(&g_total, tot);
    rb = __shfl_sync(0xffffffffu, rb, 31);
    if (i < n) {
        int st = rb + sc - sz;
        g_off[i] = st;
        for (int j = deg; j < sz; j++) g_srcs[st + j] = n;
    }
}

// ---------------------------------------------------------------------------
// K4: atomic-free scatter of src ids (no GEMM dep -> overlapped)
// ---------------------------------------------------------------------------
__global__ void k_scatter(const int* __restrict__ ei, int E) {
    int i = blockIdx.x * NBLK + threadIdx.x;
    if (i >= E) return;
    g_srcs[g_off[ei[E + i]] + g_rank[i]] = ei[i];
}

// ---------------------------------------------------------------------------
// K5: aggregation, 2 WARPS PER DESTINATION, 16-EDGE chunks per warp with all
// 20 loads batched up front (4 src int4 + 8 asrc + 8 fp16 h) for deep MLP.
// 16 lanes per edge, inline exp, corrected per-head smem exchange.
// Fused residual + BN + ReLU + classifier. Self-cleans g_cnt / g_total.
// ---------------------------------------------------------------------------
__global__ void __launch_bounds__(NBLK) k_agg(
        const float* __restrict__ gamma, const float* __restrict__ beta,
        const float* __restrict__ rmean, const float* __restrict__ rvar,
        const float* __restrict__ Wc, const float* __restrict__ bc,
        float* __restrict__ out, int n) {
    __shared__ float sW[640], sS[64], sB[64], sbc[16];
    __shared__ float4 sM[2][4][16];
    __shared__ float  sD[2][4][4];
    int tid = threadIdx.x;
    if (blockIdx.x == 0 && tid == 0) g_total = 0;
    for (int i = tid; i < 640; i += NBLK) sW[i] = Wc[i];
    if (tid < 64) {
        float sc = gamma[tid] * rsqrtf(rvar[tid] + 1e-5f);
        sS[tid] = sc;
        sB[tid] = beta[tid] - rmean[tid] * sc;
    }
    if (tid < 10) sbc[tid] = bc[tid];
    __syncthreads();

    int wid = tid >> 5, lane = tid & 31;
    int dslot = wid >> 1, half = wid & 1;
    int d = blockIdx.x * 4 + dslot;
    bool alive = (d < n);

    int sub = lane >> 4;        // which edge of the interleaved pair
    int c   = lane & 15;        // col group: cols 4c..4c+3
    int hd  = c >> 2;
    bool pb0 = hd & 1, pb1 = hd & 2;

#define SELH(v) (pb1 ? (pb0 ? (v).w : (v).z) : (pb0 ? (v).y : (v).x))

    float4 m = make_float4(0.f, 0.f, 0.f, 0.f);
    float den = 0.f;

    if (alive) {
        float adl = g_adst[d * 4 + hd];
        int start = g_off[d];
        int deg = g_cnt[d];
        int dp = (deg + 15) & ~15;
        const int*    sp  = g_srcs + start;
        const float4* as4 = (const float4*)g_asrc;
        const uint2*  hp  = (const uint2*)g_hh;   // row = 16 chunks of 8B

        for (int k = half * 16; k < dp; k += 32) {  // alternate 16-edge chunks
            const int* spk = sp + k;
            int4 A0 = *(const int4*)(spk);
            int4 A1 = *(const int4*)(spk + 4);
            int4 A2 = *(const int4*)(spk + 8);
            int4 A3 = *(const int4*)(spk + 12);
            int s0 = sub ? A0.y : A0.x;
            int s1 = sub ? A0.w : A0.z;
            int s2 = sub ? A1.y : A1.x;
            int s3 = sub ? A1.w : A1.z;
            int s4 = sub ? A2.y : A2.x;
            int s5 = sub ? A2.w : A2.z;
            int s6 = sub ? A3.y : A3.x;
            int s7 = sub ? A3.w : A3.z;
            // batch all gathers (8 h + 8 asrc) before any compute
            uint2 u0 = hp[s0 * 16 + c];
            uint2 u1 = hp[s1 * 16 + c];
            uint2 u2 = hp[s2 * 16 + c];
            uint2 u3 = hp[s3 * 16 + c];
            uint2 u4 = hp[s4 * 16 + c];
            uint2 u5 = hp[s5 * 16 + c];
            uint2 u6 = hp[s6 * 16 + c];
            uint2 u7 = hp[s7 * 16 + c];
            float4 v0 = as4[s0];
            float4 v1 = as4[s1];
            float4 v2 = as4[s2];
            float4 v3 = as4[s3];
            float4 v4 = as4[s4];
            float4 v5 = as4[s5];
            float4 v6 = as4[s6];
            float4 v7 = as4[s7];
            float w0 = eweight(SELH(v0) + adl);
            float w1 = eweight(SELH(v1) + adl);
            float w2 = eweight(SELH(v2) + adl);
            float w3 = eweight(SELH(v3) + adl);
            float w4 = eweight(SELH(v4) + adl);
            float w5 = eweight(SELH(v5) + adl);
            float w6 = eweight(SELH(v6) + adl);
            float w7 = eweight(SELH(v7) + adl);
            float4 h0 = h8tof4(u0);
            float4 h1 = h8tof4(u1);
            float4 h2 = h8tof4(u2);
            float4 h3 = h8tof4(u3);
            float4 h4 = h8tof4(u4);
            float4 h5 = h8tof4(u5);
            float4 h6 = h8tof4(u6);
            float4 h7 = h8tof4(u7);
            m.x += w0 * h0.x + w1 * h1.x + w2 * h2.x + w3 * h3.x;
            m.y += w0 * h0.y + w1 * h1.y + w2 * h2.y + w3 * h3.y;
            m.z += w0 * h0.z + w1 * h1.z + w2 * h2.z + w3 * h3.z;
            m.w += w0 * h0.w + w1 * h1.w + w2 * h2.w + w3 * h3.w;
            m.x += w4 * h4.x + w5 * h5.x + w6 * h6.x + w7 * h7.x;
            m.y += w4 * h4.y + w5 * h5.y + w6 * h6.y + w7 * h7.y;
            m.z += w4 * h4.z + w5 * h5.z + w6 * h6.z + w7 * h7.z;
            m.w += w4 * h4.w + w5 * h5.w + w6 * h6.w + w7 * h7.w;
            den += ((w0 + w1) + (w2 + w3)) + ((w4 + w5) + (w6 + w7));
        }
    }
#undef SELH

    // combine the two edge-subslots within the warp
    m.x += __shfl_xor_sync(0xffffffffu, m.x, 16);
    m.y += __shfl_xor_sync(0xffffffffu, m.y, 16);
    m.z += __shfl_xor_sync(0xffffffffu, m.z, 16);
    m.w += __shfl_xor_sync(0xffffffffu, m.w, 16);
    den += __shfl_xor_sync(0xffffffffu, den, 16);

    // exchange partials between the two warps of this destination (per-head den!)
    if (sub == 0) {
        sM[half][dslot][c] = m;
        if ((lane & 3) == 0) sD[half][dslot][hd] = den;
    }
    __syncthreads();
    {
        float4 o = sM[half ^ 1][dslot][c];
        m.x += o.x; m.y += o.y; m.z += o.z; m.w += o.w;
        den += sD[half ^ 1][dslot][hd];
    }

    if (!alive || half != 0) return;
    if (lane == 0) g_cnt[d] = 0;   // self-clean (both halves read deg before the sync)

    {   // self-loop
        float w = eweight(g_asrc[d * 4 + hd] + g_adst[d * 4 + hd]);
        float4 hv = h8tof4(((const uint2*)g_hh)[d * 16 + c]);
        m.x += w * hv.x; m.y += w * hv.y; m.z += w * hv.z; m.w += w * hv.w;
        den += w;
    }

    float inv = 1.f / (den + 1e-16f);
    float4 r = ((const float4*)g_acc)[d * 16 + c];
    int c0 = 4 * c;
    float hb0 = fmaxf((r.x + m.x * inv) * sS[c0]     + sB[c0],     0.f);
    float hb1 = fmaxf((r.y + m.y * inv) * sS[c0 + 1] + sB[c0 + 1], 0.f);
    float hb2 = fmaxf((r.z + m.z * inv) * sS[c0 + 2] + sB[c0 + 2], 0.f);
    float hb3 = fmaxf((r.w + m.w * inv) * sS[c0 + 3] + sB[c0 + 3], 0.f);

    float lg[10];
#pragma unroll
    for (int cc = 0; cc < 10; cc++)
        lg[cc] = hb0 * sW[c0 * 10 + cc]        + hb1 * sW[(c0 + 1) * 10 + cc]
               + hb2 * sW[(c0 + 2) * 10 + cc]  + hb3 * sW[(c0 + 3) * 10 + cc];
#pragma unroll
    for (int off = 8; off; off >>= 1)
#pragma unroll
        for (int cc = 0; cc < 10; cc++)
            lg[cc] += __shfl_xor_sync(0xffffffffu, lg[cc], off);
    if (lane == 0) {
#pragma unroll
        for (int cc = 0; cc < 10; cc++) out[d * 10 + cc] = lg[cc] + sbc[cc];
    }
}

extern "C" void kernel_launch(void* const* d_in, const int* in_sizes, int n_in,
                              void* d_out, int out_size) {
    const float* x     = (const float*)d_in[0];
    const int*   ei    = (const int*)d_in[1];
    const float* Wg    = (const float*)d_in[2];
    const float* att_s = (const float*)d_in[3];
    const float* att_d = (const float*)d_in[4];
    const float* bg    = (const float*)d_in[5];
    const float* Wr    = (const float*)d_in[6];
    const float* br    = (const float*)d_in[7];
    const float* gamma = (const float*)d_in[8];
    const float* beta  = (const float*)d_in[9];
    const float* rmean = (const float*)d_in[10];
    const float* rvar  = (const float*)d_in[11];
    const float* Wc    = (const float*)d_in[12];
    const float* bc    = (const float*)d_in[13];
    float* out = (float*)d_out;

    int n = in_sizes[0] / 128;
    int E = in_sizes[1] / 2;

    int nodeB = (n + NBLK - 1) / NBLK;
    int edgeB = (E + NBLK - 1) / NBLK;
    int gemmB = (n + 31) / 32;

    static cudaStream_t s2 = nullptr;
    static cudaEvent_t evFork = nullptr, evJoin = nullptr;
    static int init_done = 0;
    if (!init_done) {
        cudaFuncSetAttribute(k_gemm, cudaFuncAttributeMaxDynamicSharedMemorySize, 81920);
        cudaStreamCreateWithFlags(&s2, cudaStreamNonBlocking);
        cudaEventCreateWithFlags(&evFork, cudaEventDisableTiming);
        cudaEventCreateWithFlags(&evJoin, cudaEventDisableTiming);
        init_done = 1;
    }

    // fork: FULL CSR build (hist + rows + scatter) overlaps with the GEMM
    cudaEventRecord(evFork, 0);
    cudaStreamWaitEvent(s2, evFork, 0);

    k_gemm<<<gemmB, NBLK, 81920>>>(x, Wg, Wr, bg, br, att_s, att_d, n);

    k_hist<<<edgeB, NBLK, 0, s2>>>(ei, E);
    k_rows<<<nodeB, NBLK, 0, s2>>>(n);
    k_scatter<<<edgeB, NBLK, 0, s2>>>(ei, E);
    cudaEventRecord(evJoin, s2);
    cudaStreamWaitEvent(0, evJoin, 0);

    k_agg<<<(n + 3) / 4, NBLK>>>(gamma, beta, rmean, rvar, Wc, bc, out, n);
}

// round 16
// speedup vs baseline: 1.0601x; 1.0601x over previous
#include <cuda_runtime.h>
#include <cuda_fp16.h>

#define MAXN 50000
#define MAXE 1600000
#define MAXEP (MAXE + 7 * MAXN)   // padded CSR capacity (rows rounded to 8)
#define NBLK 256

// ---------------- scratch (device globals; no allocation) ----------------
__device__ __half2 g_hh[(MAXN + 1) * 32]; // fp16 x@Wg; row=64 halfs=128B; row n stays 0
__device__ float   g_acc[MAXN * 64];      // x @ W_res + b_gat + b_res (fp32)
__device__ float2  g_eab[(MAXN + 1) * 4]; // (exp(a_src), exp(0.2 a_src)); row n = (0,0)
__device__ float   g_adst[MAXN * 4];
__device__ int     g_cnt[MAXN];           // in-degree (self-cleaned by k_agg)
__device__ int     g_off[MAXN];           // row starts (8-aligned)
__device__ int     g_total;               // bump counter (self-cleaned by k_agg)
__device__ int     g_rank[MAXE];          // per-edge within-dst rank
__device__ int     g_srcs[MAXEP];         // CSR src ids (+ sentinel pads)

__device__ __forceinline__ float4 h8tof4(uint2 u) {
    __half2 lo = *reinterpret_cast<__half2*>(&u.x);
    __half2 hi = *reinterpret_cast<__half2*>(&u.y);
    float2 a = __half22float2(lo), b = __half22float2(hi);
    return make_float4(a.x, a.y, b.x, b.y);
}
__device__ __forceinline__ unsigned long long pack2(float v) {
    unsigned long long r;
    asm("mov.b64 %0, {%1, %1};" : "=l"(r) : "f"(v));
    return r;
}
__device__ __forceinline__ void fma2(unsigned long long& acc, unsigned long long a,
                                     unsigned long long b) {
    asm("fma.rn.f32x2 %0, %1, %2, %0;" : "+l"(acc) : "l"(a), "l"(b));
}
__device__ __forceinline__ float2 unpack2(unsigned long long v) {
    float2 r;
    asm("mov.b64 {%0, %1}, %2;" : "=f"(r.x), "=f"(r.y) : "l"(v));
    return r;
}

// ---------------------------------------------------------------------------
// K1: fused dual GEMM with packed f32x2 FMAs (proven R14 skeleton):
//   g_hh = fp16(x@Wg), g_eab = (exp(a_src), exp(0.2 a_src)),
//   g_acc = x@Wr + b_gat + b_res, g_adst raw.
// ---------------------------------------------------------------------------
__global__ void k_gemm(const float* __restrict__ x,
                       const float* __restrict__ Wg, const float* __restrict__ Wr,
                       const float* __restrict__ b0, const float* __restrict__ b1,
                       const float* __restrict__ att_s, const float* __restrict__ att_d,
                       int n) {
    extern __shared__ float sm[];
    float* sWg = sm;
    float* sWr = sm + 8192;
    float* xs  = sm + 16384;
    int tid = threadIdx.x;
    for (int i = tid; i < 8192; i += NBLK) { sWg[i] = Wg[i]; sWr[i] = Wr[i]; }
    int base = blockIdx.x * 32;
    const float4* x4 = (const float4*)x;
    for (int i = tid; i < 32 * 32; i += NBLK) {
        int node = i >> 5, kk = i & 31;
        float4 v = make_float4(0.f, 0.f, 0.f, 0.f);
        if (base + node < n) v = x4[(base + node) * 32 + kk];
        ((float4*)xs)[i] = v;
    }
    __syncthreads();

    int tx = tid & 31;
    int ty = tid >> 5;
    unsigned long long AG[4] = {0ull, 0ull, 0ull, 0ull};
    unsigned long long AR[4] = {0ull, 0ull, 0ull, 0ull};
    const float* xp = xs + ty * 4 * 128;
    const unsigned long long* wgp = (const unsigned long long*)sWg;  // 32 ull per k-row
    const unsigned long long* wrp = (const unsigned long long*)sWr;
#pragma unroll 4
    for (int k = 0; k < 128; k++) {
        unsigned long long wg = wgp[k * 32 + tx];
        unsigned long long wr = wrp[k * 32 + tx];
#pragma unroll
        for (int i = 0; i < 4; i++) {
            unsigned long long xx = pack2(xp[i * 128 + k]);
            fma2(AG[i], wg, xx);
            fma2(AR[i], wr, xx);
        }
    }

    float bias0 = b0[2 * tx] + b1[2 * tx];
    float bias1 = b0[2 * tx + 1] + b1[2 * tx + 1];
    float as0 = att_s[2 * tx], as1 = att_s[2 * tx + 1];
    float ad0 = att_d[2 * tx], ad1 = att_d[2 * tx + 1];
    int hd = tx >> 3;
#pragma unroll
    for (int i = 0; i < 4; i++) {
        int node = base + ty * 4 + i;
        float2 g = unpack2(AG[i]);
        float2 r = unpack2(AR[i]);
        float ps = g.x * as0 + g.y * as1;
        float pd = g.x * ad0 + g.y * ad1;
#pragma unroll
        for (int off = 4; off; off >>= 1) {
            ps += __shfl_xor_sync(0xffffffffu, ps, off);
            pd += __shfl_xor_sync(0xffffffffu, pd, off);
        }
        if (node < n) {
            g_hh[node * 32 + tx] = __floats2half2_rn(g.x, g.y);
            ((float2*)(g_acc + node * 64))[tx] = make_float2(r.x + bias0, r.y + bias1);
            if ((tx & 7) == 0) {
                g_eab[node * 4 + hd] = make_float2(__expf(ps), __expf(0.2f * ps));
                g_adst[node * 4 + hd] = pd;
            }
        }
    }
}

// ---------------------------------------------------------------------------
// K2: degree histogram + per-edge rank capture (overlapped with GEMM)
// ---------------------------------------------------------------------------
__global__ void k_hist(const int* __restrict__ ei, int E) {
    int i = blockIdx.x * NBLK + threadIdx.x;
    if (i < E) g_rank[i] = atomicAdd(&g_cnt[ei[E + i]], 1);
}

// ---------------------------------------------------------------------------
// K3: row starts (warp bump alloc, rows padded to 8; pads src = n sentinel).
// Also writes the sentinel eab row (0,0) -> w = 0.
// ---------------------------------------------------------------------------
__global__ void k_rows(int n) {
    int i = blockIdx.x * NBLK + threadIdx.x;
    int lane = threadIdx.x & 31;
    if (i < 4) g_eab[n * 4 + i] = make_float2(0.f, 0.f);   // sentinel: weight -> 0
    int deg = (i < n) ? g_cnt[i] : 0;
    int sz = (deg + 7) & ~7;
    int sc = sz;
#pragma unroll
    for (int off = 1; off < 32; off <<= 1) {
        int t = __shfl_up_sync(0xffffffffu, sc, off);
        if (lane >= off) sc += t;
    }
    int tot = __shfl_sync(0xffffffffu, sc, 31);
    int rb = 0;
    if (lane == 31) rb = atomicAdd(&g_total, tot);
    rb = __shfl_sync(0xffffffffu, rb, 31);
    if (i < n) {
        int st = rb + sc - sz;
        g_off[i] = st;
        for (int j = deg; j < sz; j++) g_srcs[st + j] = n;
    }
}

// ---------------------------------------------------------------------------
// K4: atomic-free scatter of src ids (no GEMM dep -> overlapped)
// ---------------------------------------------------------------------------
__global__ void k_scatter(const int* __restrict__ ei, int E) {
    int i = blockIdx.x * NBLK + threadIdx.x;
    if (i >= E) return;
    g_srcs[g_off[ei[E + i]] + g_rank[i]] = ei[i];
}

// ---------------------------------------------------------------------------
// K5: aggregation, 2 WARPS PER DESTINATION (alternating 8-edge chunks),
// 16 lanes per edge, fp16 h rows (1 line each). Weight via monotone-exp
// identity: w = max(ea_s*ea_d, eb_s*eb_d) -- NO exp in the inner loop.
// Corrected per-head smem exchange. Fused residual+BN+ReLU+classifier.
// Self-cleans g_cnt / g_total.
// ---------------------------------------------------------------------------
__global__ void __launch_bounds__(NBLK) k_agg(
        const float* __restrict__ gamma, const float* __restrict__ beta,
        const float* __restrict__ rmean, const float* __restrict__ rvar,
        const float* __restrict__ Wc, const float* __restrict__ bc,
        float* __restrict__ out, int n) {
    __shared__ float sW[640], sS[64], sB[64], sbc[16];
    __shared__ float4 sM[2][4][16];
    __shared__ float  sD[2][4][4];
    int tid = threadIdx.x;
    if (blockIdx.x == 0 && tid == 0) g_total = 0;
    for (int i = tid; i < 640; i += NBLK) sW[i] = Wc[i];
    if (tid < 64) {
        float sc = gamma[tid] * rsqrtf(rvar[tid] + 1e-5f);
        sS[tid] = sc;
        sB[tid] = beta[tid] - rmean[tid] * sc;
    }
    if (tid < 10) sbc[tid] = bc[tid];
    __syncthreads();

    int wid = tid >> 5, lane = tid & 31;
    int dslot = wid >> 1, half = wid & 1;
    int d = blockIdx.x * 4 + dslot;
    bool alive = (d < n);

    int sub = lane >> 4;        // which edge of the interleaved pair
    int c   = lane & 15;        // col group: cols 4c..4c+3
    int hd  = c >> 2;

    float4 m = make_float4(0.f, 0.f, 0.f, 0.f);
    float den = 0.f;

    if (alive) {
        float adl = g_adst[d * 4 + hd];
        float ead = __expf(adl);
        float ebd = __expf(0.2f * adl);
        int start = g_off[d];
        int deg = g_cnt[d];
        int dp = (deg + 7) & ~7;
        const int*    sp = g_srcs + start;
        const float2* ep = (const float2*)g_eab;
        const uint2*  hp = (const uint2*)g_hh;   // row = 16 chunks of 8B

        for (int k = half * 8; k < dp; k += 16) {   // alternate 8-edge chunks
            int4 a = *(const int4*)(sp + k);
            int4 b = *(const int4*)(sp + k + 4);
            int s0 = sub ? a.y : a.x;
            int s1 = sub ? a.w : a.z;
            int s2 = sub ? b.y : b.x;
            int s3 = sub ? b.w : b.z;
            float2 e0 = ep[s0 * 4 + hd];
            float2 e1 = ep[s1 * 4 + hd];
            float2 e2 = ep[s2 * 4 + hd];
            float2 e3 = ep[s3 * 4 + hd];
            uint2 u0 = hp[s0 * 16 + c];
            uint2 u1 = hp[s1 * 16 + c];
            uint2 u2 = hp[s2 * 16 + c];
            uint2 u3 = hp[s3 * 16 + c];
            float w0 = fmaxf(e0.x * ead, e0.y * ebd);
            float w1 = fmaxf(e1.x * ead, e1.y * ebd);
            float w2 = fmaxf(e2.x * ead, e2.y * ebd);
            float w3 = fmaxf(e3.x * ead, e3.y * ebd);
            float4 h0 = h8tof4(u0);
            float4 h1 = h8tof4(u1);
            float4 h2 = h8tof4(u2);
            float4 h3 = h8tof4(u3);
            m.x += w0 * h0.x + w1 * h1.x + w2 * h2.x + w3 * h3.x;
            m.y += w0 * h0.y + w1 * h1.y + w2 * h2.y + w3 * h3.y;
            m.z += w0 * h0.z + w1 * h1.z + w2 * h2.z + w3 * h3.z;
            m.w += w0 * h0.w + w1 * h1.w + w2 * h2.w + w3 * h3.w;
            den += (w0 + w1) + (w2 + w3);
        }
    }

    // combine the two edge-subslots within the warp
    m.x += __shfl_xor_sync(0xffffffffu, m.x, 16);
    m.y += __shfl_xor_sync(0xffffffffu, m.y, 16);
    m.z += __shfl_xor_sync(0xffffffffu, m.z, 16);
    m.w += __shfl_xor_sync(0xffffffffu, m.w, 16);
    den += __shfl_xor_sync(0xffffffffu, den, 16);

    // exchange partials between the two warps of this destination (per-head den!)
    if (sub == 0) {
        sM[half][dslot][c] = m;
        if ((lane & 3) == 0) sD[half][dslot][hd] = den;
    }
    __syncthreads();
    {
        float4 o = sM[half ^ 1][dslot][c];
        m.x += o.x; m.y += o.y; m.z += o.z; m.w += o.w;
        den += sD[half ^ 1][dslot][hd];
    }

    if (!alive || half != 0) return;
    if (lane == 0) g_cnt[d] = 0;   // self-clean (both halves read deg before the sync)

    {   // self-loop via the same identity
        float adl = g_adst[d * 4 + hd];
        float2 e = g_eab[d * 4 + hd];
        float w = fmaxf(e.x * __expf(adl), e.y * __expf(0.2f * adl));
        float4 hv = h8tof4(((const uint2*)g_hh)[d * 16 + c]);
        m.x += w * hv.x; m.y += w * hv.y; m.z += w * hv.z; m.w += w * hv.w;
        den += w;
    }

    float inv = 1.f / (den + 1e-16f);
    float4 r = ((const float4*)g_acc)[d * 16 + c];
    int c0 = 4 * c;
    float hb0 = fmaxf((r.x + m.x * inv) * sS[c0]     + sB[c0],     0.f);
    float hb1 = fmaxf((r.y + m.y * inv) * sS[c0 + 1] + sB[c0 + 1], 0.f);
    float hb2 = fmaxf((r.z + m.z * inv) * sS[c0 + 2] + sB[c0 + 2], 0.f);
    float hb3 = fmaxf((r.w + m.w * inv) * sS[c0 + 3] + sB[c0 + 3], 0.f);

    float lg[10];
#pragma unroll
    for (int cc = 0; cc < 10; cc++)
        lg[cc] = hb0 * sW[c0 * 10 + cc]        + hb1 * sW[(c0 + 1) * 10 + cc]
               + hb2 * sW[(c0 + 2) * 10 + cc]  + hb3 * sW[(c0 + 3) * 10 + cc];
#pragma unroll
    for (int off = 8; off; off >>= 1)
#pragma unroll
        for (int cc = 0; cc < 10; cc++)
            lg[cc] += __shfl_xor_sync(0xffffffffu, lg[cc], off);
    if (lane == 0) {
#pragma unroll
        for (int cc = 0; cc < 10; cc++) out[d * 10 + cc] = lg[cc] + sbc[cc];
    }
}

extern "C" void kernel_launch(void* const* d_in, const int* in_sizes, int n_in,
                              void* d_out, int out_size) {
    const float* x     = (const float*)d_in[0];
    const int*   ei    = (const int*)d_in[1];
    const float* Wg    = (const float*)d_in[2];
    const float* att_s = (const float*)d_in[3];
    const float* att_d = (const float*)d_in[4];
    const float* bg    = (const float*)d_in[5];
    const float* Wr    = (const float*)d_in[6];
    const float* br    = (const float*)d_in[7];
    const float* gamma = (const float*)d_in[8];
    const float* beta  = (const float*)d_in[9];
    const float* rmean = (const float*)d_in[10];
    const float* rvar  = (const float*)d_in[11];
    const float* Wc    = (const float*)d_in[12];
    const float* bc    = (const float*)d_in[13];
    float* out = (float*)d_out;

    int n = in_sizes[0] / 128;
    int E = in_sizes[1] / 2;

    int nodeB = (n + NBLK - 1) / NBLK;
    int edgeB = (E + NBLK - 1) / NBLK;
    int gemmB = (n + 31) / 32;

    static cudaStream_t s2 = nullptr;
    static cudaEvent_t evFork = nullptr, evJoin = nullptr;
    static int init_done = 0;
    if (!init_done) {
        cudaFuncSetAttribute(k_gemm, cudaFuncAttributeMaxDynamicSharedMemorySize, 81920);
        cudaStreamCreateWithFlags(&s2, cudaStreamNonBlocking);
        cudaEventCreateWithFlags(&evFork, cudaEventDisableTiming);
        cudaEventCreateWithFlags(&evJoin, cudaEventDisableTiming);
        init_done = 1;
    }

    // fork: FULL CSR build (hist + rows + scatter) overlaps with the GEMM
    cudaEventRecord(evFork, 0);
    cudaStreamWaitEvent(s2, evFork, 0);

    k_gemm<<<gemmB, NBLK, 81920>>>(x, Wg, Wr, bg, br, att_s, att_d, n);

    k_hist<<<edgeB, NBLK, 0, s2>>>(ei, E);
    k_rows<<<nodeB, NBLK, 0, s2>>>(n);
    k_scatter<<<edgeB, NBLK, 0, s2>>>(ei, E);
    cudaEventRecord(evJoin, s2);
    cudaStreamWaitEvent(0, evJoin, 0);

    k_agg<<<(n + 3) / 4, NBLK>>>(gamma, beta, rmean, rvar, Wc, bc, out, n);
}

// round 17
// speedup vs baseline: 1.1309x; 1.0668x over previous
#include <cuda_runtime.h>
#include <cuda_fp16.h>

#define MAXN 50000
#define MAXE 1600000
#define MAXEP (MAXE + 3 * MAXN)   // padded CSR capacity (rows rounded to 4)
#define NBLK 256

// ---------------- scratch (device globals; no allocation) ----------------
__device__ __half2 g_hh[(MAXN + 1) * 32]; // fp16 x@Wg; row=64 halfs=128B; row n stays 0
__device__ float   g_acc[MAXN * 64];      // x @ W_res + b_gat + b_res (fp32)
__device__ float2  g_eab[(MAXN + 1) * 4]; // (exp(a_src), exp(0.2 a_src)); row n = (0,0)
__device__ float   g_adst[MAXN * 4];
__device__ int     g_cnt[MAXN];           // in-degree (self-cleaned by k_agg)
__device__ int     g_off[MAXN];           // row starts (4-aligned)
__device__ int     g_total;               // bump counter (self-cleaned by k_agg)
__device__ int     g_rank[MAXE];          // per-edge within-dst rank
__device__ int     g_srcs[MAXEP];         // CSR src ids (+ sentinel pads)

__device__ __forceinline__ float4 h8tof4(uint2 u) {
    __half2 lo = *reinterpret_cast<__half2*>(&u.x);
    __half2 hi = *reinterpret_cast<__half2*>(&u.y);
    float2 a = __half22float2(lo), b = __half22float2(hi);
    return make_float4(a.x, a.y, b.x, b.y);
}
__device__ __forceinline__ unsigned long long pack2(float v) {
    unsigned long long r;
    asm("mov.b64 %0, {%1, %1};" : "=l"(r) : "f"(v));
    return r;
}
__device__ __forceinline__ void fma2(unsigned long long& acc, unsigned long long a,
                                     unsigned long long b) {
    asm("fma.rn.f32x2 %0, %1, %2, %0;" : "+l"(acc) : "l"(a), "l"(b));
}
__device__ __forceinline__ float2 unpack2(unsigned long long v) {
    float2 r;
    asm("mov.b64 {%0, %1}, %2;" : "=f"(r.x), "=f"(r.y) : "l"(v));
    return r;
}

// ---------------------------------------------------------------------------
// K1: fused dual GEMM with packed f32x2 FMAs (proven):
//   g_hh = fp16(x@Wg), g_eab = (exp(a_src), exp(0.2 a_src)),
//   g_acc = x@Wr + b_gat + b_res, g_adst raw.
// ---------------------------------------------------------------------------
__global__ void k_gemm(const float* __restrict__ x,
                       const float* __restrict__ Wg, const float* __restrict__ Wr,
                       const float* __restrict__ b0, const float* __restrict__ b1,
                       const float* __restrict__ att_s, const float* __restrict__ att_d,
                       int n) {
    extern __shared__ float sm[];
    float* sWg = sm;
    float* sWr = sm + 8192;
    float* xs  = sm + 16384;
    int tid = threadIdx.x;
    for (int i = tid; i < 8192; i += NBLK) { sWg[i] = Wg[i]; sWr[i] = Wr[i]; }
    int base = blockIdx.x * 32;
    const float4* x4 = (const float4*)x;
    for (int i = tid; i < 32 * 32; i += NBLK) {
        int node = i >> 5, kk = i & 31;
        float4 v = make_float4(0.f, 0.f, 0.f, 0.f);
        if (base + node < n) v = x4[(base + node) * 32 + kk];
        ((float4*)xs)[i] = v;
    }
    __syncthreads();

    int tx = tid & 31;
    int ty = tid >> 5;
    unsigned long long AG[4] = {0ull, 0ull, 0ull, 0ull};
    unsigned long long AR[4] = {0ull, 0ull, 0ull, 0ull};
    const float* xp = xs + ty * 4 * 128;
    const unsigned long long* wgp = (const unsigned long long*)sWg;  // 32 ull per k-row
    const unsigned long long* wrp = (const unsigned long long*)sWr;
#pragma unroll 4
    for (int k = 0; k < 128; k++) {
        unsigned long long wg = wgp[k * 32 + tx];
        unsigned long long wr = wrp[k * 32 + tx];
#pragma unroll
        for (int i = 0; i < 4; i++) {
            unsigned long long xx = pack2(xp[i * 128 + k]);
            fma2(AG[i], wg, xx);
            fma2(AR[i], wr, xx);
        }
    }

    float bias0 = b0[2 * tx] + b1[2 * tx];
    float bias1 = b0[2 * tx + 1] + b1[2 * tx + 1];
    float as0 = att_s[2 * tx], as1 = att_s[2 * tx + 1];
    float ad0 = att_d[2 * tx], ad1 = att_d[2 * tx + 1];
    int hd = tx >> 3;
#pragma unroll
    for (int i = 0; i < 4; i++) {
        int node = base + ty * 4 + i;
        float2 g = unpack2(AG[i]);
        float2 r = unpack2(AR[i]);
        float ps = g.x * as0 + g.y * as1;
        float pd = g.x * ad0 + g.y * ad1;
#pragma unroll
        for (int off = 4; off; off >>= 1) {
            ps += __shfl_xor_sync(0xffffffffu, ps, off);
            pd += __shfl_xor_sync(0xffffffffu, pd, off);
        }
        if (node < n) {
            g_hh[node * 32 + tx] = __floats2half2_rn(g.x, g.y);
            ((float2*)(g_acc + node * 64))[tx] = make_float2(r.x + bias0, r.y + bias1);
            if ((tx & 7) == 0) {
                g_eab[node * 4 + hd] = make_float2(__expf(ps), __expf(0.2f * ps));
                g_adst[node * 4 + hd] = pd;
            }
        }
    }
}

// ---------------------------------------------------------------------------
// K2: degree histogram + per-edge rank capture (overlapped with GEMM)
// ---------------------------------------------------------------------------
__global__ void k_hist(const int* __restrict__ ei, int E) {
    int i = blockIdx.x * NBLK + threadIdx.x;
    if (i < E) g_rank[i] = atomicAdd(&g_cnt[ei[E + i]], 1);
}

// ---------------------------------------------------------------------------
// K3: row starts (warp bump alloc, rows padded to 4; pads src = n sentinel).
// Also writes the sentinel eab row (0,0) -> w = 0.
// ---------------------------------------------------------------------------
__global__ void k_rows(int n) {
    int i = blockIdx.x * NBLK + threadIdx.x;
    int lane = threadIdx.x & 31;
    if (i < 4) g_eab[n * 4 + i] = make_float2(0.f, 0.f);   // sentinel: weight -> 0
    int deg = (i < n) ? g_cnt[i] : 0;
    int sz = (deg + 3) & ~3;
    int sc = sz;
#pragma unroll
    for (int off = 1; off < 32; off <<= 1) {
        int t = __shfl_up_sync(0xffffffffu, sc, off);
        if (lane >= off) sc += t;
    }
    int tot = __shfl_sync(0xffffffffu, sc, 31);
    int rb = 0;
    if (lane == 31) rb = atomicAdd(&g_total, tot);
    rb = __shfl_sync(0xffffffffu, rb, 31);
    if (i < n) {
        int st = rb + sc - sz;
        g_off[i] = st;
        for (int j = deg; j < sz; j++) g_srcs[st + j] = n;
    }
}

// ---------------------------------------------------------------------------
// K4: atomic-free scatter of src ids (no GEMM dep -> overlapped)
// ---------------------------------------------------------------------------
__global__ void k_scatter(const int* __restrict__ ei, int E) {
    int i = blockIdx.x * NBLK + threadIdx.x;
    if (i >= E) return;
    g_srcs[g_off[ei[E + i]] + g_rank[i]] = ei[i];
}

// ---------------------------------------------------------------------------
// K5: aggregation, 2 WARPS PER DESTINATION (alternating 8-edge chunks, plus
// one 4-edge tail owned by chunk parity). 16 lanes per edge, fp16 h rows,
// weights via monotone-exp identity (no exp in loop). Per-head smem exchange.
// Fused residual + BN + ReLU + classifier. Self-cleans g_cnt / g_total.
// ---------------------------------------------------------------------------
__global__ void __launch_bounds__(NBLK) k_agg(
        const float* __restrict__ gamma, const float* __restrict__ beta,
        const float* __restrict__ rmean, const float* __restrict__ rvar,
        const float* __restrict__ Wc, const float* __restrict__ bc,
        float* __restrict__ out, int n) {
    __shared__ float sW[640], sS[64], sB[64], sbc[16];
    __shared__ float4 sM[2][4][16];
    __shared__ float  sD[2][4][4];
    int tid = threadIdx.x;
    if (blockIdx.x == 0 && tid == 0) g_total = 0;
    for (int i = tid; i < 640; i += NBLK) sW[i] = Wc[i];
    if (tid < 64) {
        float sc = gamma[tid] * rsqrtf(rvar[tid] + 1e-5f);
        sS[tid] = sc;
        sB[tid] = beta[tid] - rmean[tid] * sc;
    }
    if (tid < 10) sbc[tid] = bc[tid];
    __syncthreads();

    int wid = tid >> 5, lane = tid & 31;
    int dslot = wid >> 1, half = wid & 1;
    int d = blockIdx.x * 4 + dslot;
    bool alive = (d < n);

    int sub = lane >> 4;        // which edge of the interleaved pair
    int c   = lane & 15;        // col group: cols 4c..4c+3
    int hd  = c >> 2;

    float4 m = make_float4(0.f, 0.f, 0.f, 0.f);
    float den = 0.f;

    if (alive) {
        float adl = g_adst[d * 4 + hd];
        float ead = __expf(adl);
        float ebd = __expf(0.2f * adl);
        int start = g_off[d];
        int deg = g_cnt[d];
        int dp = (deg + 3) & ~3;
        int full = dp & ~7;                    // whole 8-chunks
        const int*    sp = g_srcs + start;
        const float2* ep = (const float2*)g_eab;
        const uint2*  hp = (const uint2*)g_hh;   // row = 16 chunks of 8B

        for (int k = half * 8; k < full; k += 16) {   // alternate 8-edge chunks
            int4 a = *(const int4*)(sp + k);
            int4 b = *(const int4*)(sp + k + 4);
            int s0 = sub ? a.y : a.x;
            int s1 = sub ? a.w : a.z;
            int s2 = sub ? b.y : b.x;
            int s3 = sub ? b.w : b.z;
            float2 e0 = ep[s0 * 4 + hd];
            float2 e1 = ep[s1 * 4 + hd];
            float2 e2 = ep[s2 * 4 + hd];
            float2 e3 = ep[s3 * 4 + hd];
            uint2 u0 = hp[s0 * 16 + c];
            uint2 u1 = hp[s1 * 16 + c];
            uint2 u2 = hp[s2 * 16 + c];
            uint2 u3 = hp[s3 * 16 + c];
            float w0 = fmaxf(e0.x * ead, e0.y * ebd);
            float w1 = fmaxf(e1.x * ead, e1.y * ebd);
            float w2 = fmaxf(e2.x * ead, e2.y * ebd);
            float w3 = fmaxf(e3.x * ead, e3.y * ebd);
            float4 h0 = h8tof4(u0);
            float4 h1 = h8tof4(u1);
            float4 h2 = h8tof4(u2);
            float4 h3 = h8tof4(u3);
            m.x += w0 * h0.x + w1 * h1.x + w2 * h2.x + w3 * h3.x;
            m.y += w0 * h0.y + w1 * h1.y + w2 * h2.y + w3 * h3.y;
            m.z += w0 * h0.z + w1 * h1.z + w2 * h2.z + w3 * h3.z;
            m.w += w0 * h0.w + w1 * h1.w + w2 * h2.w + w3 * h3.w;
            den += (w0 + w1) + (w2 + w3);
        }
        if ((dp & 4) && half == ((full >> 3) & 1)) {   // one 4-edge tail chunk
            int4 a = *(const int4*)(sp + full);
            int s0 = sub ? a.y : a.x;
            int s1 = sub ? a.w : a.z;
            float2 e0 = ep[s0 * 4 + hd];
            float2 e1 = ep[s1 * 4 + hd];
            uint2 u0 = hp[s0 * 16 + c];
            uint2 u1 = hp[s1 * 16 + c];
            float w0 = fmaxf(e0.x * ead, e0.y * ebd);
            float w1 = fmaxf(e1.x * ead, e1.y * ebd);
            float4 h0 = h8tof4(u0);
            float4 h1 = h8tof4(u1);
            m.x += w0 * h0.x + w1 * h1.x;
            m.y += w0 * h0.y + w1 * h1.y;
            m.z += w0 * h0.z + w1 * h1.z;
            m.w += w0 * h0.w + w1 * h1.w;
            den += w0 + w1;
        }
    }

    // combine the two edge-subslots within the warp
    m.x += __shfl_xor_sync(0xffffffffu, m.x, 16);
    m.y += __shfl_xor_sync(0xffffffffu, m.y, 16);
    m.z += __shfl_xor_sync(0xffffffffu, m.z, 16);
    m.w += __shfl_xor_sync(0xffffffffu, m.w, 16);
    den += __shfl_xor_sync(0xffffffffu, den, 16);

    // exchange partials between the two warps of this destination (per-head den!)
    if (sub == 0) {
        sM[half][dslot][c] = m;
        if ((lane & 3) == 0) sD[half][dslot][hd] = den;
    }
    __syncthreads();
    {
        float4 o = sM[half ^ 1][dslot][c];
        m.x += o.x; m.y += o.y; m.z += o.z; m.w += o.w;
        den += sD[half ^ 1][dslot][hd];
    }

    if (!alive || half != 0) return;
    if (lane == 0) g_cnt[d] = 0;   // self-clean (both halves read deg before the sync)

    {   // self-loop via the same identity
        float adl = g_adst[d * 4 + hd];
        float2 e = g_eab[d * 4 + hd];
        float w = fmaxf(e.x * __expf(adl), e.y * __expf(0.2f * adl));
        float4 hv = h8tof4(((const uint2*)g_hh)[d * 16 + c]);
        m.x += w * hv.x; m.y += w * hv.y; m.z += w * hv.z; m.w += w * hv.w;
        den += w;
    }

    float inv = 1.f / (den + 1e-16f);
    float4 r = ((const float4*)g_acc)[d * 16 + c];
    int c0 = 4 * c;
    float hb0 = fmaxf((r.x + m.x * inv) * sS[c0]     + sB[c0],     0.f);
    float hb1 = fmaxf((r.y + m.y * inv) * sS[c0 + 1] + sB[c0 + 1], 0.f);
    float hb2 = fmaxf((r.z + m.z * inv) * sS[c0 + 2] + sB[c0 + 2], 0.f);
    float hb3 = fmaxf((r.w + m.w * inv) * sS[c0 + 3] + sB[c0 + 3], 0.f);

    float lg[10];
#pragma unroll
    for (int cc = 0; cc < 10; cc++)
        lg[cc] = hb0 * sW[c0 * 10 + cc]        + hb1 * sW[(c0 + 1) * 10 + cc]
               + hb2 * sW[(c0 + 2) * 10 + cc]  + hb3 * sW[(c0 + 3) * 10 + cc];
#pragma unroll
    for (int off = 8; off; off >>= 1)
#pragma unroll
        for (int cc = 0; cc < 10; cc++)
            lg[cc] += __shfl_xor_sync(0xffffffffu, lg[cc], off);
    if (lane == 0) {
#pragma unroll
        for (int cc = 0; cc < 10; cc++) out[d * 10 + cc] = lg[cc] + sbc[cc];
    }
}

extern "C" void kernel_launch(void* const* d_in, const int* in_sizes, int n_in,
                              void* d_out, int out_size) {
    const float* x     = (const float*)d_in[0];
    const int*   ei    = (const int*)d_in[1];
    const float* Wg    = (const float*)d_in[2];
    const float* att_s = (const float*)d_in[3];
    const float* att_d = (const float*)d_in[4];
    const float* bg    = (const float*)d_in[5];
    const float* Wr    = (const float*)d_in[6];
    const float* br    = (const float*)d_in[7];
    const float* gamma = (const float*)d_in[8];
    const float* beta  = (const float*)d_in[9];
    const float* rmean = (const float*)d_in[10];
    const float* rvar  = (const float*)d_in[11];
    const float* Wc    = (const float*)d_in[12];
    const float* bc    = (const float*)d_in[13];
    float* out = (float*)d_out;

    int n = in_sizes[0] / 128;
    int E = in_sizes[1] / 2;

    int nodeB = (n + NBLK - 1) / NBLK;
    int edgeB = (E + NBLK - 1) / NBLK;
    int gemmB = (n + 31) / 32;

    static cudaStream_t s2 = nullptr;
    static cudaEvent_t evFork = nullptr, evJoin = nullptr;
    static int init_done = 0;
    if (!init_done) {
        cudaFuncSetAttribute(k_gemm, cudaFuncAttributeMaxDynamicSharedMemorySize, 81920);
        cudaStreamCreateWithFlags(&s2, cudaStreamNonBlocking);
        cudaEventCreateWithFlags(&evFork, cudaEventDisableTiming);
        cudaEventCreateWithFlags(&evJoin, cudaEventDisableTiming);
        init_done = 1;
    }

    // fork: FULL CSR build (hist + rows + scatter) overlaps with the GEMM
    cudaEventRecord(evFork, 0);
    cudaStreamWaitEvent(s2, evFork, 0);

    k_gemm<<<gemmB, NBLK, 81920>>>(x, Wg, Wr, bg, br, att_s, att_d, n);

    k_hist<<<edgeB, NBLK, 0, s2>>>(ei, E);
    k_rows<<<nodeB, NBLK, 0, s2>>>(n);
    k_scatter<<<edgeB, NBLK, 0, s2>>>(ei, E);
    cudaEventRecord(evJoin, s2);
    cudaStreamWaitEvent(0, evJoin, 0);

    k_agg<<<(n + 3) / 4, NBLK>>>(gamma, beta, rmean, rvar, Wc, bc, out, n);
}